// round 6
// baseline (speedup 1.0000x reference)
#include <cuda_runtime.h>
#include <cuda_bf16.h>
#include <cuda_fp16.h>
#include <math.h>
#include <stdint.h>

#define F 256
#define NW 512           // fused B width: [W_self | W]
#define N_MAX 50048
#define E_MAX 800256

// -------- device scratch --------
__device__ float g_sin[N_MAX];               // in_deg^-1/2
__device__ float g_outr[N_MAX];              // out_deg^-1/2
__device__ int   g_cnt[N_MAX];
__device__ int   g_outd[N_MAX];
__device__ int   g_fill[N_MAX];
__device__ int   g_scan[N_MAX];
__device__ int   g_roff[N_MAX + 1];
__device__ int   g_esrc[E_MAX];
__device__ float g_esc[E_MAX];
__device__ int   g_bsums[64];

__device__ __nv_bfloat16 g_featH[(size_t)N_MAX * F];
__device__ __nv_bfloat16 g_featL[(size_t)N_MAX * F];
__device__ __nv_bfloat16 g_wbH[F * NW];      // [k][n512] = [W_self | W]
__device__ __nv_bfloat16 g_wbL[F * NW];
__device__ __half        g_h1[(size_t)N_MAX * F];   // feature@W, fp16

// -------- helpers --------
__device__ __forceinline__ unsigned pk(__nv_bfloat16 a, __nv_bfloat16 b) {
    __nv_bfloat162 t = __halves2bfloat162(a, b);
    return *(unsigned*)&t;
}
__device__ __forceinline__ void cvt_hl(float x, __nv_bfloat16& h, __nv_bfloat16& l) {
    h = __float2bfloat16(x);
    l = __float2bfloat16(x - __bfloat162float(h));
}
__device__ __forceinline__ uint32_t sptr(const void* p) {
    return (uint32_t)__cvta_generic_to_shared(p);
}
__device__ __forceinline__ void ldsm4(unsigned r[4], uint32_t a) {
    asm volatile("ldmatrix.sync.aligned.m8n8.x4.shared.b16 {%0,%1,%2,%3}, [%4];\n"
        : "=r"(r[0]), "=r"(r[1]), "=r"(r[2]), "=r"(r[3]) : "r"(a));
}
__device__ __forceinline__ void ldsm4t(unsigned r[4], uint32_t a) {
    asm volatile("ldmatrix.sync.aligned.m8n8.x4.trans.shared.b16 {%0,%1,%2,%3}, [%4];\n"
        : "=r"(r[0]), "=r"(r[1]), "=r"(r[2]), "=r"(r[3]) : "r"(a));
}
__device__ __forceinline__ void mma_bf16(float* d, const unsigned a[4],
                                         unsigned b0, unsigned b1) {
    asm volatile(
        "mma.sync.aligned.m16n8k16.row.col.f32.bf16.bf16.f32 "
        "{%0,%1,%2,%3}, {%4,%5,%6,%7}, {%8,%9}, {%0,%1,%2,%3};\n"
        : "+f"(d[0]), "+f"(d[1]), "+f"(d[2]), "+f"(d[3])
        : "r"(a[0]), "r"(a[1]), "r"(a[2]), "r"(a[3]), "r"(b0), "r"(b1));
}
__device__ __forceinline__ void cp16(uint32_t dst, const void* src) {
    asm volatile("cp.async.cg.shared.global [%0], [%1], 16;\n" :: "r"(dst), "l"(src));
}
__device__ __forceinline__ void cp16z(uint32_t dst, const void* src, int sz) {
    asm volatile("cp.async.cg.shared.global [%0], [%1], 16, %2;\n"
                 :: "r"(dst), "l"(src), "r"(sz));
}
__device__ __forceinline__ void cp_commit() {
    asm volatile("cp.async.commit_group;\n" ::: "memory");
}
__device__ __forceinline__ void cp_wait0() {
    asm volatile("cp.async.wait_group 0;\n" ::: "memory");
}

// ---------------- CSR chain (side stream) ----------------
__global__ void zero_kernel(int n) {
    int i = blockIdx.x * blockDim.x + threadIdx.x;
    if (i < n) { g_cnt[i] = 0; g_outd[i] = 0; }
}
__global__ void hist_kernel(const int* __restrict__ src,
                            const int* __restrict__ dst, int e) {
    int i = blockIdx.x * blockDim.x + threadIdx.x;
    if (i < e) {
        atomicAdd(&g_cnt[dst[i]], 1);
        atomicAdd(&g_outd[src[i]], 1);
    }
}
__global__ void scan1_kernel(int n) {
    __shared__ int sh[1024];
    int t = threadIdx.x;
    int i = blockIdx.x * 1024 + t;
    int v = (i < n) ? g_cnt[i] : 0;
    sh[t] = v; __syncthreads();
    #pragma unroll
    for (int off = 1; off < 1024; off <<= 1) {
        int x = sh[t];
        if (t >= off) x += sh[t - off];
        __syncthreads();
        sh[t] = x;
        __syncthreads();
    }
    if (i < n) g_scan[i] = sh[t];
    if (t == 1023) g_bsums[blockIdx.x] = sh[t];
}
__global__ void scan23_kernel(int n, int nb) {
    __shared__ int pre[64];
    if (threadIdx.x == 0) {
        int a = 0;
        for (int j = 0; j < nb; ++j) { pre[j] = a; a += g_bsums[j]; }
    }
    __syncthreads();
    int i = blockIdx.x * blockDim.x + threadIdx.x;
    if (i < n) {
        int cnt = g_cnt[i];
        int incl = g_scan[i] + pre[i >> 10];
        g_roff[i + 1] = incl;
        g_fill[i] = incl - cnt;
        g_outr[i] = rsqrtf(fmaxf((float)g_outd[i], 1.0f));
        g_sin[i]  = rsqrtf(fmaxf((float)cnt, 1.0f));
        if (i == 0) g_roff[0] = 0;
    }
}
__global__ void fill_kernel(const int* __restrict__ src,
                            const int* __restrict__ dst,
                            const float* __restrict__ e_w,
                            float* __restrict__ out_tail, int e) {
    int i = blockIdx.x * blockDim.x + threadIdx.x;
    if (i < e) {
        float w = e_w[i];
        int s = src[i];
        int p = atomicAdd(&g_fill[dst[i]], 1);
        g_esrc[p] = s;
        g_esc[p] = w * g_outr[s];
        out_tail[i] = w;               // e_w passthrough output
    }
}

// ---------------- conversions (main stream) ----------------
__global__ void convertC_kernel(const float* __restrict__ feat,
                                const float* __restrict__ Ws,
                                const float* __restrict__ Wn,
                                int q, int CB) {
    int b = blockIdx.x, t = threadIdx.x;
    if (b < CB) {
        int i = b * 256 + t;
        if (i < q) {
            float4 v = ((const float4*)feat)[i];
            __nv_bfloat16 h0, h1, h2, h3, l0, l1, l2, l3;
            cvt_hl(v.x, h0, l0); cvt_hl(v.y, h1, l1);
            cvt_hl(v.z, h2, l2); cvt_hl(v.w, h3, l3);
            ((uint2*)g_featH)[i] = make_uint2(pk(h0, h1), pk(h2, h3));
            ((uint2*)g_featL)[i] = make_uint2(pk(l0, l1), pk(l2, l3));
        }
    } else {
        int i = (b - CB) * 256 + t;
        if (i < F * F) {
            int k = i >> 8, nn = i & 255;
            __nv_bfloat16 h, l;
            cvt_hl(Ws[i], h, l);
            g_wbH[k * NW + nn] = h; g_wbL[k * NW + nn] = l;
            cvt_hl(Wn[i], h, l);
            g_wbH[k * NW + 256 + nn] = h; g_wbL[k * NW + 256 + nn] = l;
        }
    }
}

// ---------------- persistent bf16 3-term GEMM -----------------
// Y[n,512] = feature @ [W_self | W]; cols 0-255 -> out (fp32, h_s),
// cols 256-511 -> g_h1 (fp16). Tiles 128x128, K=256 (8 iters of 32).
#define A_STRIDE 40
#define B_STRIDE 136
#define ST_ELEMS 18944           // 128*40*2 + 32*136*2
#define AH_OFF(s) ((s) * ST_ELEMS)
#define AL_OFF(s) ((s) * ST_ELEMS + 5120)
#define BH_OFF(s) ((s) * ST_ELEMS + 10240)
#define BL_OFF(s) ((s) * ST_ELEMS + 14592)
#define SMEM_DYN (2 * ST_ELEMS * 2)

__device__ __forceinline__ void load_stage(uint32_t sb, int stage, int git,
                                           int bx, int G, int n, int NT, int tid) {
    int t = bx + (git >> 3) * G;
    if (t >= NT) return;
    int mBase = (t >> 2) * 128;
    int nBase = (t & 3) * 128;
    int k0 = (git & 7) * 32;
    #pragma unroll
    for (int u = 0; u < 2; ++u) {
        int idx = u * 256 + tid;
        int row = idx >> 2, un = idx & 3;
        int gr = mBase + row;
        int grc = min(gr, n - 1);
        size_t go = (size_t)grc * F + k0 + un * 8;
        int sz = (gr < n) ? 16 : 0;
        uint32_t doff = (uint32_t)(row * A_STRIDE + un * 8) * 2;
        cp16z(sb + (uint32_t)AH_OFF(stage) * 2 + doff, g_featH + go, sz);
        cp16z(sb + (uint32_t)AL_OFF(stage) * 2 + doff, g_featL + go, sz);
    }
    #pragma unroll
    for (int u = 0; u < 2; ++u) {
        int idx = u * 256 + tid;
        int row = idx >> 4, un = idx & 15;
        size_t go = (size_t)(k0 + row) * NW + nBase + un * 8;
        uint32_t doff = (uint32_t)(row * B_STRIDE + un * 8) * 2;
        cp16(sb + (uint32_t)BH_OFF(stage) * 2 + doff, g_wbH + go);
        cp16(sb + (uint32_t)BL_OFF(stage) * 2 + doff, g_wbL + go);
    }
}

__global__ void __launch_bounds__(256, 2)
gemm_persist(float* __restrict__ out, int n, int NT) {
    extern __shared__ __align__(128) char smraw[];
    __nv_bfloat16* base = (__nv_bfloat16*)smraw;
    uint32_t sb = sptr(smraw);

    int tid = threadIdx.x;
    int wid = tid >> 5, lane = tid & 31;
    int wm = wid & 3, wn = wid >> 2;
    int bx = blockIdx.x, G = gridDim.x;

    int tiles_this = (NT - bx + G - 1) / G;
    if (tiles_this <= 0) return;
    int gitEnd = tiles_this * 8;

    float acc[2][8][4];
    #pragma unroll
    for (int i = 0; i < 2; ++i)
        #pragma unroll
        for (int j = 0; j < 8; ++j)
            #pragma unroll
            for (int q = 0; q < 4; ++q) acc[i][j][q] = 0.f;

    load_stage(sb, 0, 0, bx, G, n, NT, tid);
    cp_commit();

    #pragma unroll 1
    for (int git = 0; git < gitEnd; ++git) {
        cp_wait0();
        __syncthreads();
        if (git + 1 < gitEnd) {
            load_stage(sb, (git + 1) & 1, git + 1, bx, G, n, NT, tid);
            cp_commit();
        }
        int st = git & 1;
        #pragma unroll
        for (int kt = 0; kt < 2; ++kt) {
            int ks = kt * 16;
            unsigned aH[2][4], aL[2][4];
            #pragma unroll
            for (int mt = 0; mt < 2; ++mt) {
                int r = wm * 32 + mt * 16 + (lane & 15);
                int c = ks + (lane >> 4) * 8;
                ldsm4(aH[mt], sptr(base + AH_OFF(st) + r * A_STRIDE + c));
                ldsm4(aL[mt], sptr(base + AL_OFF(st) + r * A_STRIDE + c));
            }
            #pragma unroll
            for (int nc = 0; nc < 4; ++nc) {
                int rB = ks + (lane & 15);
                int cB = wn * 64 + nc * 16 + (lane >> 4) * 8;
                unsigned bH[4], bL[4];
                ldsm4t(bH, sptr(base + BH_OFF(st) + rB * B_STRIDE + cB));
                ldsm4t(bL, sptr(base + BL_OFF(st) + rB * B_STRIDE + cB));
                #pragma unroll
                for (int mt = 0; mt < 2; ++mt) {
                    mma_bf16(acc[mt][nc * 2],     aH[mt], bH[0], bH[1]);
                    mma_bf16(acc[mt][nc * 2],     aL[mt], bH[0], bH[1]);
                    mma_bf16(acc[mt][nc * 2],     aH[mt], bL[0], bL[1]);
                    mma_bf16(acc[mt][nc * 2 + 1], aH[mt], bH[2], bH[3]);
                    mma_bf16(acc[mt][nc * 2 + 1], aL[mt], bH[2], bH[3]);
                    mma_bf16(acc[mt][nc * 2 + 1], aH[mt], bL[2], bL[3]);
                }
            }
        }
        if ((git & 7) == 7) {
            // epilogue for tile t
            int t = bx + (git >> 3) * G;
            int mBase = (t >> 2) * 128;
            int tn = t & 3;
            #pragma unroll
            for (int mt = 0; mt < 2; ++mt) {
                int r0 = mBase + wm * 32 + mt * 16 + (lane >> 2);
                int r1 = r0 + 8;
                #pragma unroll
                for (int nt = 0; nt < 8; ++nt) {
                    int cl = wn * 64 + nt * 8 + (lane & 3) * 2;   // col in tile
                    float* d = acc[mt][nt];
                    if (tn < 2) {
                        int c = tn * 128 + cl;
                        if (r0 < n)
                            *(float2*)(out + (size_t)r0 * F + c) = make_float2(d[0], d[1]);
                        if (r1 < n)
                            *(float2*)(out + (size_t)r1 * F + c) = make_float2(d[2], d[3]);
                    } else {
                        int c = (tn - 2) * 128 + cl;
                        if (r0 < n) {
                            __half2 v = __floats2half2_rn(d[0], d[1]);
                            *(unsigned*)(g_h1 + (size_t)r0 * F + c) = *(unsigned*)&v;
                        }
                        if (r1 < n) {
                            __half2 v = __floats2half2_rn(d[2], d[3]);
                            *(unsigned*)(g_h1 + (size_t)r1 * F + c) = *(unsigned*)&v;
                        }
                    }
                    d[0] = d[1] = d[2] = d[3] = 0.f;
                }
            }
        }
    }
}

// ---------------- final: out = h_s + si*(S . h1) + si*b ----------------
__global__ void __launch_bounds__(512)
final_kernel(const float* __restrict__ bias, float* __restrict__ out, int n) {
    int row  = blockIdx.x * 16 + (threadIdx.x >> 5);
    int lane = threadIdx.x & 31;
    if (row >= n) return;
    int beg = g_roff[row], end = g_roff[row + 1];
    float a[8];
    #pragma unroll
    for (int j = 0; j < 8; ++j) a[j] = 0.f;
    for (int base = beg; base < end; base += 32) {
        int m = min(32, end - base);
        int sE = 0; float cE = 0.f;
        if (lane < m) { sE = g_esrc[base + lane]; cE = g_esc[base + lane]; }
        #pragma unroll 4
        for (int j = 0; j < m; ++j) {
            int   ss = __shfl_sync(0xffffffffu, sE, j);
            float sc = __shfl_sync(0xffffffffu, cE, j);
            uint4 d = *(const uint4*)(g_h1 + (size_t)ss * F + lane * 8);
            float2 f0 = __half22float2(*(__half2*)&d.x);
            float2 f1 = __half22float2(*(__half2*)&d.y);
            float2 f2 = __half22float2(*(__half2*)&d.z);
            float2 f3 = __half22float2(*(__half2*)&d.w);
            a[0] += f0.x * sc; a[1] += f0.y * sc;
            a[2] += f1.x * sc; a[3] += f1.y * sc;
            a[4] += f2.x * sc; a[5] += f2.y * sc;
            a[6] += f3.x * sc; a[7] += f3.y * sc;
        }
    }
    float si = g_sin[row];
    float* op = out + (size_t)row * F + lane * 8;
    float4 o0 = *(float4*)(op);
    float4 o1 = *(float4*)(op + 4);
    float4 b0 = *(const float4*)(bias + lane * 8);
    float4 b1 = *(const float4*)(bias + lane * 8 + 4);
    o0.x += si * (a[0] + b0.x); o0.y += si * (a[1] + b0.y);
    o0.z += si * (a[2] + b0.z); o0.w += si * (a[3] + b0.w);
    o1.x += si * (a[4] + b1.x); o1.y += si * (a[5] + b1.y);
    o1.z += si * (a[6] + b1.z); o1.w += si * (a[7] + b1.w);
    *(float4*)(op)     = o0;
    *(float4*)(op + 4) = o1;
}

// ---------------- launch ----------------
extern "C" void kernel_launch(void* const* d_in, const int* in_sizes, int n_in,
                              void* d_out, int out_size) {
    const float* feature = (const float*)d_in[0];
    const float* e_w     = (const float*)d_in[1];
    const float* W_self  = (const float*)d_in[4];
    const float* W       = (const float*)d_in[5];
    const float* b       = (const float*)d_in[6];
    const int*   src     = (const int*)d_in[7];
    const int*   dst     = (const int*)d_in[8];
    float*       out     = (float*)d_out;

    int n = in_sizes[0] / F;
    int e = in_sizes[1];
    int q = n * (F / 4);

    static bool init = false;
    static cudaStream_t s2 = 0;
    static cudaEvent_t ev1 = 0, ev2 = 0;
    if (!init) {
        cudaFuncSetAttribute(gemm_persist,
                             cudaFuncAttributeMaxDynamicSharedMemorySize, SMEM_DYN);
        cudaStreamCreateWithFlags(&s2, cudaStreamNonBlocking);
        cudaEventCreateWithFlags(&ev1, cudaEventDisableTiming);
        cudaEventCreateWithFlags(&ev2, cudaEventDisableTiming);
        init = true;
    }

    // main stream: the one being captured (per-thread default), else legacy.
    cudaStream_t ms = 0;
    {
        cudaStreamCaptureStatus cs = cudaStreamCaptureStatusNone;
        if (cudaStreamIsCapturing(cudaStreamPerThread, &cs) == cudaSuccess &&
            cs == cudaStreamCaptureStatusActive)
            ms = cudaStreamPerThread;
    }

    // fork side stream for the CSR chain
    cudaEventRecord(ev1, ms);
    cudaStreamWaitEvent(s2, ev1, 0);

    zero_kernel<<<(n + 255) / 256, 256, 0, s2>>>(n);
    hist_kernel<<<(e + 255) / 256, 256, 0, s2>>>(src, dst, e);
    int nb = (n + 1023) / 1024;
    scan1_kernel<<<nb, 1024, 0, s2>>>(n);
    scan23_kernel<<<(n + 255) / 256, 256, 0, s2>>>(n, nb);
    fill_kernel<<<(e + 255) / 256, 256, 0, s2>>>(src, dst, e_w,
                                                 out + (size_t)n * F, e);
    cudaEventRecord(ev2, s2);

    // main stream: convert -> persistent GEMM
    int CB = (q + 255) / 256;
    int WB = (F * F + 255) / 256;
    convertC_kernel<<<CB + WB, 256, 0, ms>>>(feature, W_self, W, q, CB);

    int NT = ((n + 127) / 128) * 4;
    gemm_persist<<<296, 256, SMEM_DYN, ms>>>(out, n, NT);

    // join + final
    cudaStreamWaitEvent(ms, ev2, 0);
    final_kernel<<<(n + 15) / 16, 512, 0, ms>>>(b, out, n);
}

// round 7
// speedup vs baseline: 1.1880x; 1.1880x over previous
#include <cuda_runtime.h>
#include <cuda_bf16.h>
#include <cuda_fp16.h>
#include <math.h>
#include <stdint.h>

#define F 256
#define NW 512           // fused B width: [W_self | W]
#define N_MAX 50048
#define E_MAX 800256

// -------- device scratch --------
__device__ float g_sin[N_MAX];               // in_deg^-1/2
__device__ float g_outr[N_MAX];              // out_deg^-1/2
__device__ int   g_cnt[N_MAX];
__device__ int   g_outd[N_MAX];
__device__ int   g_fill[N_MAX];
__device__ int   g_scan[N_MAX];
__device__ int   g_roff[N_MAX + 1];
__device__ int   g_esrc[E_MAX];
__device__ float g_esc[E_MAX];
__device__ int   g_bsums[64];

__device__ __half g_featH[(size_t)N_MAX * F];       // fp16 hi
__device__ __half g_featL[(size_t)N_MAX * F];       // fp16 residual
__device__ __half g_wb[F * NW];                     // [k][n512] = [W_self | W]
__device__ __half g_h1[(size_t)N_MAX * F];          // feature@W (fp16)

// -------- helpers --------
__device__ __forceinline__ uint32_t sptr(const void* p) {
    return (uint32_t)__cvta_generic_to_shared(p);
}
__device__ __forceinline__ void ldsm4(unsigned r[4], uint32_t a) {
    asm volatile("ldmatrix.sync.aligned.m8n8.x4.shared.b16 {%0,%1,%2,%3}, [%4];\n"
        : "=r"(r[0]), "=r"(r[1]), "=r"(r[2]), "=r"(r[3]) : "r"(a));
}
__device__ __forceinline__ void ldsm4t(unsigned r[4], uint32_t a) {
    asm volatile("ldmatrix.sync.aligned.m8n8.x4.trans.shared.b16 {%0,%1,%2,%3}, [%4];\n"
        : "=r"(r[0]), "=r"(r[1]), "=r"(r[2]), "=r"(r[3]) : "r"(a));
}
__device__ __forceinline__ void mma_f16(float* d, const unsigned a[4],
                                        unsigned b0, unsigned b1) {
    asm volatile(
        "mma.sync.aligned.m16n8k16.row.col.f32.f16.f16.f32 "
        "{%0,%1,%2,%3}, {%4,%5,%6,%7}, {%8,%9}, {%0,%1,%2,%3};\n"
        : "+f"(d[0]), "+f"(d[1]), "+f"(d[2]), "+f"(d[3])
        : "r"(a[0]), "r"(a[1]), "r"(a[2]), "r"(a[3]), "r"(b0), "r"(b1));
}
__device__ __forceinline__ void cp16(uint32_t dst, const void* src) {
    asm volatile("cp.async.cg.shared.global [%0], [%1], 16;\n" :: "r"(dst), "l"(src));
}
__device__ __forceinline__ void cp16z(uint32_t dst, const void* src, int sz) {
    asm volatile("cp.async.cg.shared.global [%0], [%1], 16, %2;\n"
                 :: "r"(dst), "l"(src), "r"(sz));
}
__device__ __forceinline__ void cp_commit() {
    asm volatile("cp.async.commit_group;\n" ::: "memory");
}
__device__ __forceinline__ void cp_wait1() {
    asm volatile("cp.async.wait_group 1;\n" ::: "memory");
}
__device__ __forceinline__ void cp_wait0() {
    asm volatile("cp.async.wait_group 0;\n" ::: "memory");
}

// ---------------- CSR chain (side stream) ----------------
__global__ void zero_kernel(int n) {
    int i = blockIdx.x * blockDim.x + threadIdx.x;
    if (i < n) { g_cnt[i] = 0; g_outd[i] = 0; }
}
__global__ void hist_kernel(const int* __restrict__ src,
                            const int* __restrict__ dst, int e) {
    int i = blockIdx.x * blockDim.x + threadIdx.x;
    if (i < e) {
        atomicAdd(&g_cnt[dst[i]], 1);
        atomicAdd(&g_outd[src[i]], 1);
    }
}
__global__ void scan1_kernel(int n) {
    __shared__ int sh[1024];
    int t = threadIdx.x;
    int i = blockIdx.x * 1024 + t;
    int v = (i < n) ? g_cnt[i] : 0;
    sh[t] = v; __syncthreads();
    #pragma unroll
    for (int off = 1; off < 1024; off <<= 1) {
        int x = sh[t];
        if (t >= off) x += sh[t - off];
        __syncthreads();
        sh[t] = x;
        __syncthreads();
    }
    if (i < n) g_scan[i] = sh[t];
    if (t == 1023) g_bsums[blockIdx.x] = sh[t];
}
__global__ void scan23_kernel(int n, int nb) {
    __shared__ int pre[64];
    if (threadIdx.x == 0) {
        int a = 0;
        for (int j = 0; j < nb; ++j) { pre[j] = a; a += g_bsums[j]; }
    }
    __syncthreads();
    int i = blockIdx.x * blockDim.x + threadIdx.x;
    if (i < n) {
        int cnt = g_cnt[i];
        int incl = g_scan[i] + pre[i >> 10];
        g_roff[i + 1] = incl;
        g_fill[i] = incl - cnt;
        g_outr[i] = rsqrtf(fmaxf((float)g_outd[i], 1.0f));
        g_sin[i]  = rsqrtf(fmaxf((float)cnt, 1.0f));
        if (i == 0) g_roff[0] = 0;
    }
}
__global__ void fill_kernel(const int* __restrict__ src,
                            const int* __restrict__ dst,
                            const float* __restrict__ e_w,
                            float* __restrict__ out_tail, int e) {
    int i = blockIdx.x * blockDim.x + threadIdx.x;
    if (i < e) {
        float w = e_w[i];
        int s = src[i];
        int p = atomicAdd(&g_fill[dst[i]], 1);
        g_esrc[p] = s;
        g_esc[p] = w * g_outr[s];
        out_tail[i] = w;               // e_w passthrough output
    }
}

// ---------------- conversions (main stream) ----------------
__global__ void convertC_kernel(const float* __restrict__ feat,
                                const float* __restrict__ Ws,
                                const float* __restrict__ Wn,
                                int q, int CB) {
    int b = blockIdx.x, t = threadIdx.x;
    if (b < CB) {
        int i = b * 256 + t;
        if (i < q) {
            float4 v = ((const float4*)feat)[i];
            __half h0 = __float2half_rn(v.x), h1 = __float2half_rn(v.y);
            __half h2 = __float2half_rn(v.z), h3 = __float2half_rn(v.w);
            __half l0 = __float2half_rn(v.x - __half2float(h0));
            __half l1 = __float2half_rn(v.y - __half2float(h1));
            __half l2 = __float2half_rn(v.z - __half2float(h2));
            __half l3 = __float2half_rn(v.w - __half2float(h3));
            __half2 H0 = __halves2half2(h0, h1), H1 = __halves2half2(h2, h3);
            __half2 L0 = __halves2half2(l0, l1), L1 = __halves2half2(l2, l3);
            ((uint2*)g_featH)[i] = make_uint2(*(unsigned*)&H0, *(unsigned*)&H1);
            ((uint2*)g_featL)[i] = make_uint2(*(unsigned*)&L0, *(unsigned*)&L1);
        }
    } else {
        int i = (b - CB) * 256 + t;
        if (i < F * F) {
            int k = i >> 8, nn = i & 255;
            g_wb[k * NW + nn]       = __float2half_rn(Ws[i]);
            g_wb[k * NW + 256 + nn] = __float2half_rn(Wn[i]);
        }
    }
}

// ---------------- fp16 2-term GEMM (mma.sync, 3-stage cp.async) -----------
// Y[n,512] = feature @ [W_self | W]; cols 0-255 -> out (fp32 h_s),
// cols 256-511 -> g_h1 (fp16). One CTA per 128x128 tile, K=256 (8 iters).
#define A_STRIDE 40
#define B_STRIDE 136
#define ST_ELEMS 14592           // 2*128*40 + 32*136
#define AH_OFF(s) ((s) * ST_ELEMS)
#define AL_OFF(s) ((s) * ST_ELEMS + 5120)
#define BH_OFF(s) ((s) * ST_ELEMS + 10240)
#define NSTAGE 3
#define SMEM_DYN (NSTAGE * ST_ELEMS * 2)

__device__ __forceinline__ void load_stage(uint32_t sb, int stage, int it,
                                           int mBase, int nBase, int n, int tid) {
    int k0 = it * 32;
    #pragma unroll
    for (int u = 0; u < 2; ++u) {
        int idx = u * 256 + tid;
        int row = idx >> 2, un = idx & 3;
        int gr = mBase + row;
        int grc = min(gr, n - 1);
        size_t go = (size_t)grc * F + k0 + un * 8;
        int sz = (gr < n) ? 16 : 0;
        uint32_t doff = (uint32_t)(row * A_STRIDE + un * 8) * 2;
        cp16z(sb + (uint32_t)AH_OFF(stage) * 2 + doff, g_featH + go, sz);
        cp16z(sb + (uint32_t)AL_OFF(stage) * 2 + doff, g_featL + go, sz);
    }
    #pragma unroll
    for (int u = 0; u < 2; ++u) {
        int idx = u * 256 + tid;
        int row = idx >> 4, un = idx & 15;
        size_t go = (size_t)(k0 + row) * NW + nBase + un * 8;
        uint32_t doff = (uint32_t)(row * B_STRIDE + un * 8) * 2;
        cp16(sb + (uint32_t)BH_OFF(stage) * 2 + doff, g_wb + go);
    }
}

__global__ void __launch_bounds__(256, 2)
gemm_kernel(float* __restrict__ out, int n) {
    extern __shared__ __align__(128) char smraw[];
    __half* base = (__half*)smraw;
    uint32_t sb = sptr(smraw);

    int tid = threadIdx.x;
    int wid = tid >> 5, lane = tid & 31;
    int wm = wid & 3, wn = wid >> 2;
    int t = blockIdx.x;
    int mBase = (t >> 2) * 128;
    int tn = t & 3;
    int nBase = tn * 128;

    float acc[2][8][4];
    #pragma unroll
    for (int i = 0; i < 2; ++i)
        #pragma unroll
        for (int j = 0; j < 8; ++j)
            #pragma unroll
            for (int q = 0; q < 4; ++q) acc[i][j][q] = 0.f;

    load_stage(sb, 0, 0, mBase, nBase, n, tid); cp_commit();
    load_stage(sb, 1, 1, mBase, nBase, n, tid); cp_commit();

    #pragma unroll 1
    for (int it = 0; it < 8; ++it) {
        if (it < 7) cp_wait1(); else cp_wait0();
        __syncthreads();
        int st = it % NSTAGE;
        #pragma unroll
        for (int kt = 0; kt < 2; ++kt) {
            int ks = kt * 16;
            unsigned aH[2][4], aL[2][4];
            #pragma unroll
            for (int mt = 0; mt < 2; ++mt) {
                int r = wm * 32 + mt * 16 + (lane & 15);
                int c = ks + (lane >> 4) * 8;
                ldsm4(aH[mt], sptr(base + AH_OFF(st) + r * A_STRIDE + c));
                ldsm4(aL[mt], sptr(base + AL_OFF(st) + r * A_STRIDE + c));
            }
            #pragma unroll
            for (int nc = 0; nc < 4; ++nc) {
                int rB = ks + (lane & 15);
                int cB = wn * 64 + nc * 16 + (lane >> 4) * 8;
                unsigned bH[4];
                ldsm4t(bH, sptr(base + BH_OFF(st) + rB * B_STRIDE + cB));
                #pragma unroll
                for (int mt = 0; mt < 2; ++mt) {
                    mma_f16(acc[mt][nc * 2],     aH[mt], bH[0], bH[1]);
                    mma_f16(acc[mt][nc * 2],     aL[mt], bH[0], bH[1]);
                    mma_f16(acc[mt][nc * 2 + 1], aH[mt], bH[2], bH[3]);
                    mma_f16(acc[mt][nc * 2 + 1], aL[mt], bH[2], bH[3]);
                }
            }
        }
        if (it + 2 < 8) {
            load_stage(sb, (it + 2) % NSTAGE, it + 2, mBase, nBase, n, tid);
            cp_commit();
        }
    }

    // epilogue: cols 0-255 -> out (h_s), cols 256-511 -> g_h1 (fp16)
    #pragma unroll
    for (int mt = 0; mt < 2; ++mt) {
        int r0 = mBase + wm * 32 + mt * 16 + (lane >> 2);
        int r1 = r0 + 8;
        #pragma unroll
        for (int nt = 0; nt < 8; ++nt) {
            int cl = wn * 64 + nt * 8 + (lane & 3) * 2;
            float* d = acc[mt][nt];
            if (tn < 2) {
                int c = tn * 128 + cl;
                if (r0 < n)
                    *(float2*)(out + (size_t)r0 * F + c) = make_float2(d[0], d[1]);
                if (r1 < n)
                    *(float2*)(out + (size_t)r1 * F + c) = make_float2(d[2], d[3]);
            } else {
                int c = (tn - 2) * 128 + cl;
                if (r0 < n) {
                    __half2 v = __floats2half2_rn(d[0], d[1]);
                    *(unsigned*)(g_h1 + (size_t)r0 * F + c) = *(unsigned*)&v;
                }
                if (r1 < n) {
                    __half2 v = __floats2half2_rn(d[2], d[3]);
                    *(unsigned*)(g_h1 + (size_t)r1 * F + c) = *(unsigned*)&v;
                }
            }
        }
    }
}

// ---------------- final: out = h_s + si*(S . h1) + si*b ----------------
__global__ void __launch_bounds__(512)
final_kernel(const float* __restrict__ bias, float* __restrict__ out, int n) {
    int row  = blockIdx.x * 16 + (threadIdx.x >> 5);
    int lane = threadIdx.x & 31;
    if (row >= n) return;
    int beg = g_roff[row], end = g_roff[row + 1];
    float a[8];
    #pragma unroll
    for (int j = 0; j < 8; ++j) a[j] = 0.f;
    for (int base = beg; base < end; base += 32) {
        int m = min(32, end - base);
        int sE = 0; float cE = 0.f;
        if (lane < m) { sE = g_esrc[base + lane]; cE = g_esc[base + lane]; }
        #pragma unroll 4
        for (int j = 0; j < m; ++j) {
            int   ss = __shfl_sync(0xffffffffu, sE, j);
            float sc = __shfl_sync(0xffffffffu, cE, j);
            uint4 d = *(const uint4*)(g_h1 + (size_t)ss * F + lane * 8);
            float2 f0 = __half22float2(*(__half2*)&d.x);
            float2 f1 = __half22float2(*(__half2*)&d.y);
            float2 f2 = __half22float2(*(__half2*)&d.z);
            float2 f3 = __half22float2(*(__half2*)&d.w);
            a[0] += f0.x * sc; a[1] += f0.y * sc;
            a[2] += f1.x * sc; a[3] += f1.y * sc;
            a[4] += f2.x * sc; a[5] += f2.y * sc;
            a[6] += f3.x * sc; a[7] += f3.y * sc;
        }
    }
    float si = g_sin[row];
    float* op = out + (size_t)row * F + lane * 8;
    float4 o0 = *(float4*)(op);
    float4 o1 = *(float4*)(op + 4);
    float4 b0 = *(const float4*)(bias + lane * 8);
    float4 b1 = *(const float4*)(bias + lane * 8 + 4);
    o0.x += si * (a[0] + b0.x); o0.y += si * (a[1] + b0.y);
    o0.z += si * (a[2] + b0.z); o0.w += si * (a[3] + b0.w);
    o1.x += si * (a[4] + b1.x); o1.y += si * (a[5] + b1.y);
    o1.z += si * (a[6] + b1.z); o1.w += si * (a[7] + b1.w);
    *(float4*)(op)     = o0;
    *(float4*)(op + 4) = o1;
}

// ---------------- launch ----------------
extern "C" void kernel_launch(void* const* d_in, const int* in_sizes, int n_in,
                              void* d_out, int out_size) {
    const float* feature = (const float*)d_in[0];
    const float* e_w     = (const float*)d_in[1];
    const float* W_self  = (const float*)d_in[4];
    const float* W       = (const float*)d_in[5];
    const float* b       = (const float*)d_in[6];
    const int*   src     = (const int*)d_in[7];
    const int*   dst     = (const int*)d_in[8];
    float*       out     = (float*)d_out;

    int n = in_sizes[0] / F;
    int e = in_sizes[1];
    int q = n * (F / 4);

    static bool init = false;
    static cudaStream_t s2 = 0;
    static cudaEvent_t ev1 = 0, ev2 = 0;
    if (!init) {
        cudaFuncSetAttribute(gemm_kernel,
                             cudaFuncAttributeMaxDynamicSharedMemorySize, SMEM_DYN);
        cudaStreamCreateWithFlags(&s2, cudaStreamNonBlocking);
        cudaEventCreateWithFlags(&ev1, cudaEventDisableTiming);
        cudaEventCreateWithFlags(&ev2, cudaEventDisableTiming);
        init = true;
    }

    cudaStream_t ms = 0;
    {
        cudaStreamCaptureStatus cs = cudaStreamCaptureStatusNone;
        if (cudaStreamIsCapturing(cudaStreamPerThread, &cs) == cudaSuccess &&
            cs == cudaStreamCaptureStatusActive)
            ms = cudaStreamPerThread;
    }

    // fork side stream for the CSR chain (overlaps with convert + GEMM waves)
    cudaEventRecord(ev1, ms);
    cudaStreamWaitEvent(s2, ev1, 0);

    zero_kernel<<<(n + 255) / 256, 256, 0, s2>>>(n);
    hist_kernel<<<(e + 255) / 256, 256, 0, s2>>>(src, dst, e);
    int nb = (n + 1023) / 1024;
    scan1_kernel<<<nb, 1024, 0, s2>>>(n);
    scan23_kernel<<<(n + 255) / 256, 256, 0, s2>>>(n, nb);
    fill_kernel<<<(e + 255) / 256, 256, 0, s2>>>(src, dst, e_w,
                                                 out + (size_t)n * F, e);
    cudaEventRecord(ev2, s2);

    // main stream: convert -> tiled GEMM
    int CB = (q + 255) / 256;
    int WB = (F * F + 255) / 256;
    convertC_kernel<<<CB + WB, 256, 0, ms>>>(feature, W_self, W, q, CB);

    int NT = ((n + 127) / 128) * 4;
    gemm_kernel<<<NT, 256, SMEM_DYN, ms>>>(out, n);

    // join + final
    cudaStreamWaitEvent(ms, ev2, 0);
    final_kernel<<<(n + 15) / 16, 512, 0, ms>>>(b, out, n);
}

// round 8
// speedup vs baseline: 1.2191x; 1.0262x over previous
#include <cuda_runtime.h>
#include <cuda_bf16.h>
#include <cuda_fp16.h>
#include <math.h>
#include <stdint.h>

#define F 256
#define NW 512           // fused B width: [W_self | W]
#define N_MAX 50048
#define E_MAX 800256

// -------- device scratch --------
__device__ float g_sin[N_MAX];               // in_deg^-1/2
__device__ float g_outr[N_MAX];              // out_deg^-1/2
__device__ int   g_cnt[N_MAX];
__device__ int   g_outd[N_MAX];
__device__ int   g_fill[N_MAX];
__device__ int   g_scan[N_MAX];
__device__ int   g_roff[N_MAX + 1];
__device__ int   g_esrc[E_MAX];
__device__ float g_esc[E_MAX];
__device__ int   g_bsums[64];

__device__ __half g_featH[(size_t)N_MAX * F];       // fp16 hi
__device__ __half g_featL[(size_t)N_MAX * F];       // fp16 residual
__device__ __half g_wb[F * NW];                     // [k][n512] = [W_self | W]
__device__ __half g_h1[(size_t)N_MAX * F];          // feature@W (fp16)

// -------- helpers --------
__device__ __forceinline__ uint32_t sptr(const void* p) {
    return (uint32_t)__cvta_generic_to_shared(p);
}
__device__ __forceinline__ void ldsm4(unsigned r[4], uint32_t a) {
    asm volatile("ldmatrix.sync.aligned.m8n8.x4.shared.b16 {%0,%1,%2,%3}, [%4];\n"
        : "=r"(r[0]), "=r"(r[1]), "=r"(r[2]), "=r"(r[3]) : "r"(a));
}
__device__ __forceinline__ void ldsm4t(unsigned r[4], uint32_t a) {
    asm volatile("ldmatrix.sync.aligned.m8n8.x4.trans.shared.b16 {%0,%1,%2,%3}, [%4];\n"
        : "=r"(r[0]), "=r"(r[1]), "=r"(r[2]), "=r"(r[3]) : "r"(a));
}
__device__ __forceinline__ void mma_f16(float* d, const unsigned a[4],
                                        unsigned b0, unsigned b1) {
    asm volatile(
        "mma.sync.aligned.m16n8k16.row.col.f32.f16.f16.f32 "
        "{%0,%1,%2,%3}, {%4,%5,%6,%7}, {%8,%9}, {%0,%1,%2,%3};\n"
        : "+f"(d[0]), "+f"(d[1]), "+f"(d[2]), "+f"(d[3])
        : "r"(a[0]), "r"(a[1]), "r"(a[2]), "r"(a[3]), "r"(b0), "r"(b1));
}
__device__ __forceinline__ void cp16(uint32_t dst, const void* src) {
    asm volatile("cp.async.cg.shared.global [%0], [%1], 16;\n" :: "r"(dst), "l"(src));
}
__device__ __forceinline__ void cp16z(uint32_t dst, const void* src, int sz) {
    asm volatile("cp.async.cg.shared.global [%0], [%1], 16, %2;\n"
                 :: "r"(dst), "l"(src), "r"(sz));
}
__device__ __forceinline__ void cp_commit() {
    asm volatile("cp.async.commit_group;\n" ::: "memory");
}
__device__ __forceinline__ void cp_wait1() {
    asm volatile("cp.async.wait_group 1;\n" ::: "memory");
}
__device__ __forceinline__ void cp_wait0() {
    asm volatile("cp.async.wait_group 0;\n" ::: "memory");
}

// ---------------- CSR chain (side stream) ----------------
__global__ void zero_kernel(int n) {
    int i = blockIdx.x * blockDim.x + threadIdx.x;
    if (i < n) { g_cnt[i] = 0; g_outd[i] = 0; }
}
__global__ void hist_kernel(const int* __restrict__ src,
                            const int* __restrict__ dst, int e) {
    int i = blockIdx.x * blockDim.x + threadIdx.x;
    if (i < e) {
        atomicAdd(&g_cnt[dst[i]], 1);
        atomicAdd(&g_outd[src[i]], 1);
    }
}
__global__ void scan1_kernel(int n) {
    __shared__ int sh[1024];
    int t = threadIdx.x;
    int i = blockIdx.x * 1024 + t;
    int v = (i < n) ? g_cnt[i] : 0;
    sh[t] = v; __syncthreads();
    #pragma unroll
    for (int off = 1; off < 1024; off <<= 1) {
        int x = sh[t];
        if (t >= off) x += sh[t - off];
        __syncthreads();
        sh[t] = x;
        __syncthreads();
    }
    if (i < n) g_scan[i] = sh[t];
    if (t == 1023) g_bsums[blockIdx.x] = sh[t];
}
__global__ void scan23_kernel(int n, int nb) {
    __shared__ int pre[64];
    if (threadIdx.x == 0) {
        int a = 0;
        for (int j = 0; j < nb; ++j) { pre[j] = a; a += g_bsums[j]; }
    }
    __syncthreads();
    int i = blockIdx.x * blockDim.x + threadIdx.x;
    if (i < n) {
        int cnt = g_cnt[i];
        int incl = g_scan[i] + pre[i >> 10];
        g_roff[i + 1] = incl;
        g_fill[i] = incl - cnt;
        g_outr[i] = rsqrtf(fmaxf((float)g_outd[i], 1.0f));
        g_sin[i]  = rsqrtf(fmaxf((float)cnt, 1.0f));
        if (i == 0) g_roff[0] = 0;
    }
}
__global__ void fill_kernel(const int* __restrict__ src,
                            const int* __restrict__ dst,
                            const float* __restrict__ e_w,
                            float* __restrict__ out_tail, int e) {
    int i = blockIdx.x * blockDim.x + threadIdx.x;
    if (i < e) {
        float w = e_w[i];
        int s = src[i];
        int p = atomicAdd(&g_fill[dst[i]], 1);
        g_esrc[p] = s;
        g_esc[p] = w * g_outr[s];
        out_tail[i] = w;               // e_w passthrough output
    }
}

// ---------------- conversions (main stream) ----------------
__global__ void convertC_kernel(const float* __restrict__ feat,
                                const float* __restrict__ Ws,
                                const float* __restrict__ Wn,
                                int q, int CB) {
    int b = blockIdx.x, t = threadIdx.x;
    if (b < CB) {
        int i = b * 256 + t;
        if (i < q) {
            float4 v = ((const float4*)feat)[i];
            __half h0 = __float2half_rn(v.x), h1 = __float2half_rn(v.y);
            __half h2 = __float2half_rn(v.z), h3 = __float2half_rn(v.w);
            __half l0 = __float2half_rn(v.x - __half2float(h0));
            __half l1 = __float2half_rn(v.y - __half2float(h1));
            __half l2 = __float2half_rn(v.z - __half2float(h2));
            __half l3 = __float2half_rn(v.w - __half2float(h3));
            __half2 H0 = __halves2half2(h0, h1), H1 = __halves2half2(h2, h3);
            __half2 L0 = __halves2half2(l0, l1), L1 = __halves2half2(l2, l3);
            ((uint2*)g_featH)[i] = make_uint2(*(unsigned*)&H0, *(unsigned*)&H1);
            ((uint2*)g_featL)[i] = make_uint2(*(unsigned*)&L0, *(unsigned*)&L1);
        }
    } else {
        int i = (b - CB) * 256 + t;
        if (i < F * F) {
            int k = i >> 8, nn = i & 255;
            g_wb[k * NW + nn]       = __float2half_rn(Ws[i]);
            g_wb[k * NW + 256 + nn] = __float2half_rn(Wn[i]);
        }
    }
}

// ---------------- fp16 GEMM (mma.sync, 3-stage cp.async) -------------------
// Y[n,512] = feature @ [W_self | W]; cols 0-255 (tn<2) -> out (fp32 h_s,
// 2-term hi+lo split), cols 256-511 (tn>=2) -> g_h1 (fp16, 1-term hi only —
// that path already carries fp16 storage error of the same order).
#define A_STRIDE 40
#define B_STRIDE 136
#define ST_ELEMS 14592           // 2*128*40 + 32*136
#define AH_OFF(s) ((s) * ST_ELEMS)
#define AL_OFF(s) ((s) * ST_ELEMS + 5120)
#define BH_OFF(s) ((s) * ST_ELEMS + 10240)
#define NSTAGE 3
#define SMEM_DYN (NSTAGE * ST_ELEMS * 2)

__device__ __forceinline__ void load_stage(uint32_t sb, int stage, int it,
                                           int mBase, int nBase, int n, int tid,
                                           bool needL) {
    int k0 = it * 32;
    #pragma unroll
    for (int u = 0; u < 2; ++u) {
        int idx = u * 256 + tid;
        int row = idx >> 2, un = idx & 3;
        int gr = mBase + row;
        int grc = min(gr, n - 1);
        size_t go = (size_t)grc * F + k0 + un * 8;
        int sz = (gr < n) ? 16 : 0;
        uint32_t doff = (uint32_t)(row * A_STRIDE + un * 8) * 2;
        cp16z(sb + (uint32_t)AH_OFF(stage) * 2 + doff, g_featH + go, sz);
        if (needL)
            cp16z(sb + (uint32_t)AL_OFF(stage) * 2 + doff, g_featL + go, sz);
    }
    #pragma unroll
    for (int u = 0; u < 2; ++u) {
        int idx = u * 256 + tid;
        int row = idx >> 4, un = idx & 15;
        size_t go = (size_t)(k0 + row) * NW + nBase + un * 8;
        uint32_t doff = (uint32_t)(row * B_STRIDE + un * 8) * 2;
        cp16(sb + (uint32_t)BH_OFF(stage) * 2 + doff, g_wb + go);
    }
}

__global__ void __launch_bounds__(256, 2)
gemm_kernel(float* __restrict__ out, int n) {
    extern __shared__ __align__(128) char smraw[];
    __half* base = (__half*)smraw;
    uint32_t sb = sptr(smraw);

    int tid = threadIdx.x;
    int wid = tid >> 5, lane = tid & 31;
    int wm = wid & 3, wn = wid >> 2;
    int t = blockIdx.x;
    int mBase = (t >> 2) * 128;
    int tn = t & 3;
    int nBase = tn * 128;
    const bool needL = (tn < 2);       // 2-term split only for the h_s half

    float acc[2][8][4];
    #pragma unroll
    for (int i = 0; i < 2; ++i)
        #pragma unroll
        for (int j = 0; j < 8; ++j)
            #pragma unroll
            for (int q = 0; q < 4; ++q) acc[i][j][q] = 0.f;

    load_stage(sb, 0, 0, mBase, nBase, n, tid, needL); cp_commit();
    load_stage(sb, 1, 1, mBase, nBase, n, tid, needL); cp_commit();

    #pragma unroll 1
    for (int it = 0; it < 8; ++it) {
        if (it < 7) cp_wait1(); else cp_wait0();
        __syncthreads();
        int st = it % NSTAGE;
        #pragma unroll
        for (int kt = 0; kt < 2; ++kt) {
            int ks = kt * 16;
            unsigned aH[2][4], aL[2][4];
            #pragma unroll
            for (int mt = 0; mt < 2; ++mt) {
                int r = wm * 32 + mt * 16 + (lane & 15);
                int c = ks + (lane >> 4) * 8;
                ldsm4(aH[mt], sptr(base + AH_OFF(st) + r * A_STRIDE + c));
                if (needL)
                    ldsm4(aL[mt], sptr(base + AL_OFF(st) + r * A_STRIDE + c));
            }
            #pragma unroll
            for (int nc = 0; nc < 4; ++nc) {
                int rB = ks + (lane & 15);
                int cB = wn * 64 + nc * 16 + (lane >> 4) * 8;
                unsigned bH[4];
                ldsm4t(bH, sptr(base + BH_OFF(st) + rB * B_STRIDE + cB));
                #pragma unroll
                for (int mt = 0; mt < 2; ++mt) {
                    mma_f16(acc[mt][nc * 2],     aH[mt], bH[0], bH[1]);
                    mma_f16(acc[mt][nc * 2 + 1], aH[mt], bH[2], bH[3]);
                    if (needL) {
                        mma_f16(acc[mt][nc * 2],     aL[mt], bH[0], bH[1]);
                        mma_f16(acc[mt][nc * 2 + 1], aL[mt], bH[2], bH[3]);
                    }
                }
            }
        }
        if (it + 2 < 8) {
            load_stage(sb, (it + 2) % NSTAGE, it + 2, mBase, nBase, n, tid, needL);
            cp_commit();
        }
    }

    // epilogue: cols 0-255 -> out (h_s), cols 256-511 -> g_h1 (fp16)
    #pragma unroll
    for (int mt = 0; mt < 2; ++mt) {
        int r0 = mBase + wm * 32 + mt * 16 + (lane >> 2);
        int r1 = r0 + 8;
        #pragma unroll
        for (int nt = 0; nt < 8; ++nt) {
            int cl = wn * 64 + nt * 8 + (lane & 3) * 2;
            float* d = acc[mt][nt];
            if (tn < 2) {
                int c = tn * 128 + cl;
                if (r0 < n)
                    *(float2*)(out + (size_t)r0 * F + c) = make_float2(d[0], d[1]);
                if (r1 < n)
                    *(float2*)(out + (size_t)r1 * F + c) = make_float2(d[2], d[3]);
            } else {
                int c = (tn - 2) * 128 + cl;
                if (r0 < n) {
                    __half2 v = __floats2half2_rn(d[0], d[1]);
                    *(unsigned*)(g_h1 + (size_t)r0 * F + c) = *(unsigned*)&v;
                }
                if (r1 < n) {
                    __half2 v = __floats2half2_rn(d[2], d[3]);
                    *(unsigned*)(g_h1 + (size_t)r1 * F + c) = *(unsigned*)&v;
                }
            }
        }
    }
}

// ---------------- final: out = h_s + si*(S . h1) + si*b ----------------
__global__ void __launch_bounds__(512)
final_kernel(const float* __restrict__ bias, float* __restrict__ out, int n) {
    int row  = blockIdx.x * 16 + (threadIdx.x >> 5);
    int lane = threadIdx.x & 31;
    if (row >= n) return;
    int beg = g_roff[row], end = g_roff[row + 1];
    float a[8];
    #pragma unroll
    for (int j = 0; j < 8; ++j) a[j] = 0.f;
    for (int base = beg; base < end; base += 32) {
        int m = min(32, end - base);
        int sE = 0; float cE = 0.f;
        if (lane < m) { sE = g_esrc[base + lane]; cE = g_esc[base + lane]; }
        #pragma unroll 4
        for (int j = 0; j < m; ++j) {
            int   ss = __shfl_sync(0xffffffffu, sE, j);
            float sc = __shfl_sync(0xffffffffu, cE, j);
            uint4 d = *(const uint4*)(g_h1 + (size_t)ss * F + lane * 8);
            float2 f0 = __half22float2(*(__half2*)&d.x);
            float2 f1 = __half22float2(*(__half2*)&d.y);
            float2 f2 = __half22float2(*(__half2*)&d.z);
            float2 f3 = __half22float2(*(__half2*)&d.w);
            a[0] += f0.x * sc; a[1] += f0.y * sc;
            a[2] += f1.x * sc; a[3] += f1.y * sc;
            a[4] += f2.x * sc; a[5] += f2.y * sc;
            a[6] += f3.x * sc; a[7] += f3.y * sc;
        }
    }
    float si = g_sin[row];
    float* op = out + (size_t)row * F + lane * 8;
    float4 o0 = *(float4*)(op);
    float4 o1 = *(float4*)(op + 4);
    float4 b0 = *(const float4*)(bias + lane * 8);
    float4 b1 = *(const float4*)(bias + lane * 8 + 4);
    o0.x += si * (a[0] + b0.x); o0.y += si * (a[1] + b0.y);
    o0.z += si * (a[2] + b0.z); o0.w += si * (a[3] + b0.w);
    o1.x += si * (a[4] + b1.x); o1.y += si * (a[5] + b1.y);
    o1.z += si * (a[6] + b1.z); o1.w += si * (a[7] + b1.w);
    *(float4*)(op)     = o0;
    *(float4*)(op + 4) = o1;
}

// ---------------- launch ----------------
extern "C" void kernel_launch(void* const* d_in, const int* in_sizes, int n_in,
                              void* d_out, int out_size) {
    const float* feature = (const float*)d_in[0];
    const float* e_w     = (const float*)d_in[1];
    const float* W_self  = (const float*)d_in[4];
    const float* W       = (const float*)d_in[5];
    const float* b       = (const float*)d_in[6];
    const int*   src     = (const int*)d_in[7];
    const int*   dst     = (const int*)d_in[8];
    float*       out     = (float*)d_out;

    int n = in_sizes[0] / F;
    int e = in_sizes[1];
    int q = n * (F / 4);

    static bool init = false;
    static cudaStream_t s2 = 0;
    static cudaEvent_t ev1 = 0, ev2 = 0;
    if (!init) {
        cudaFuncSetAttribute(gemm_kernel,
                             cudaFuncAttributeMaxDynamicSharedMemorySize, SMEM_DYN);
        cudaStreamCreateWithFlags(&s2, cudaStreamNonBlocking);
        cudaEventCreateWithFlags(&ev1, cudaEventDisableTiming);
        cudaEventCreateWithFlags(&ev2, cudaEventDisableTiming);
        init = true;
    }

    cudaStream_t ms = 0;
    {
        cudaStreamCaptureStatus cs = cudaStreamCaptureStatusNone;
        if (cudaStreamIsCapturing(cudaStreamPerThread, &cs) == cudaSuccess &&
            cs == cudaStreamCaptureStatusActive)
            ms = cudaStreamPerThread;
    }

    // fork side stream for the CSR chain (overlaps with convert + GEMM waves)
    cudaEventRecord(ev1, ms);
    cudaStreamWaitEvent(s2, ev1, 0);

    zero_kernel<<<(n + 255) / 256, 256, 0, s2>>>(n);
    hist_kernel<<<(e + 255) / 256, 256, 0, s2>>>(src, dst, e);
    int nb = (n + 1023) / 1024;
    scan1_kernel<<<nb, 1024, 0, s2>>>(n);
    scan23_kernel<<<(n + 255) / 256, 256, 0, s2>>>(n, nb);
    fill_kernel<<<(e + 255) / 256, 256, 0, s2>>>(src, dst, e_w,
                                                 out + (size_t)n * F, e);
    cudaEventRecord(ev2, s2);

    // main stream: convert -> tiled GEMM
    int CB = (q + 255) / 256;
    int WB = (F * F + 255) / 256;
    convertC_kernel<<<CB + WB, 256, 0, ms>>>(feature, W_self, W, q, CB);

    int NT = ((n + 127) / 128) * 4;
    gemm_kernel<<<NT, 256, SMEM_DYN, ms>>>(out, n);

    // join + final
    cudaStreamWaitEvent(ms, ev2, 0);
    final_kernel<<<(n + 15) / 16, 512, 0, ms>>>(b, out, n);
}